// round 7
// baseline (speedup 1.0000x reference)
#include <cuda_runtime.h>
#include <cstdint>

#define Bz 8
#define Tz 2048
#define Dz 1024
#define Kz 1024
#define BT (Bz*Tz)
#define NCH 8
#define LCH (Tz/NCH)     // 256

// ---------------- scratch (device globals; no allocations allowed) ----------
__device__ float g_xr[BT*Dz];
__device__ float g_xk[BT*Dz];
__device__ float g_xv[BT*Dz];
__device__ float g_r [BT*Dz];
__device__ float g_k [BT*Dz];
__device__ float g_v [BT*Dz];
__device__ float g_att[BT*Dz];
__device__ float g_W[4][Dz*Dz];          // tf32-rounded W_r,W_k,W_v,W_o
__device__ float g_chunk[Bz*NCH*Kz*2];
__device__ float g_init [Bz*NCH*Kz*2];
__device__ float g_stats[2*Bz];
__device__ float g_mean[Bz];
__device__ float g_rstd[Bz];

// ---------------- helpers ----------------------------------------------------
__device__ __forceinline__ float rtf(float x) {
    uint32_t r;
    asm("cvt.rna.tf32.f32 %0, %1;" : "=r"(r) : "f"(x));
    return __uint_as_float(r);
}
__device__ __forceinline__ void cp16(uint32_t saddr, const void* g) {
    asm volatile("cp.async.cg.shared.global [%0], [%1], 16;" :: "r"(saddr), "l"(g) : "memory");
}
#define CP_COMMIT() asm volatile("cp.async.commit_group;" ::: "memory")
#define CP_WAIT1()  asm volatile("cp.async.wait_group 1;" ::: "memory")
#define CP_WAIT0()  asm volatile("cp.async.wait_group 0;" ::: "memory")

__device__ __forceinline__ uint32_t smem_u32(const void* p) {
    uint32_t a;
    asm("{ .reg .u64 t; cvta.to.shared.u64 t, %1; cvt.u32.u64 %0, t; }" : "=r"(a) : "l"(p));
    return a;
}
__device__ __forceinline__ void mma_tf32(float* d, const uint32_t* a, const uint32_t* b) {
    asm volatile(
        "mma.sync.aligned.m16n8k8.row.col.f32.tf32.tf32.f32 "
        "{%0,%1,%2,%3}, {%4,%5,%6,%7}, {%8,%9}, {%0,%1,%2,%3};"
        : "+f"(d[0]), "+f"(d[1]), "+f"(d[2]), "+f"(d[3])
        : "r"(a[0]), "r"(a[1]), "r"(a[2]), "r"(a[3]), "r"(b[0]), "r"(b[1]));
}
__device__ __forceinline__ void ldsm4(uint32_t& r0, uint32_t& r1, uint32_t& r2, uint32_t& r3,
                                      uint32_t addr) {
    asm volatile("ldmatrix.sync.aligned.m8n8.x4.shared.b16 {%0,%1,%2,%3}, [%4];"
                 : "=r"(r0), "=r"(r1), "=r"(r2), "=r"(r3) : "r"(addr));
}

// ---------------- small kernels ----------------------------------------------
__global__ void zero_stats_kernel() {
    int i = threadIdx.x;
    if (i < 2*Bz) g_stats[i] = 0.f;
}

__global__ void round_w_kernel(const float* __restrict__ w0, const float* __restrict__ w1,
                               const float* __restrict__ w2, const float* __restrict__ w3)
{
    int m = blockIdx.y;
    const float* s = (m == 0) ? w0 : (m == 1) ? w1 : (m == 2) ? w2 : w3;
    long e = ((long)blockIdx.x * blockDim.x + threadIdx.x) * 4;
    if (e >= (long)Dz*Dz) return;
    float4 v = *(const float4*)(s + e);
    v.x = rtf(v.x); v.y = rtf(v.y); v.z = rtf(v.z); v.w = rtf(v.w);
    *(float4*)(&g_W[m][0] + e) = v;
}

__global__ void mix_kernel(const float* __restrict__ x,
                           const float* __restrict__ state,
                           const float* __restrict__ tmr,
                           const float* __restrict__ tmk,
                           const float* __restrict__ tmv)
{
    int idx = blockIdx.x * blockDim.x + threadIdx.x;
    long e = (long)idx * 4;
    if (e >= (long)BT*Dz) return;
    int d  = (int)(e & (Dz-1));
    int bt = (int)(e >> 10);
    int t  = bt & (Tz-1);
    int b  = bt >> 11;

    float4 xc = *(const float4*)(x + e);
    float4 xp;
    if (t == 0) {
        xp.x = state[(b*Kz + d + 0)*3 + 2];
        xp.y = state[(b*Kz + d + 1)*3 + 2];
        xp.z = state[(b*Kz + d + 2)*3 + 2];
        xp.w = state[(b*Kz + d + 3)*3 + 2];
    } else {
        xp = *(const float4*)(x + e - Dz);
    }
    float4 mr = *(const float4*)(tmr + d);
    float4 mk = *(const float4*)(tmk + d);
    float4 mv = *(const float4*)(tmv + d);

    float4 o;
    o.x = rtf(xc.x*mr.x + xp.x*(1.f-mr.x));
    o.y = rtf(xc.y*mr.y + xp.y*(1.f-mr.y));
    o.z = rtf(xc.z*mr.z + xp.z*(1.f-mr.z));
    o.w = rtf(xc.w*mr.w + xp.w*(1.f-mr.w));
    *(float4*)(g_xr + e) = o;

    o.x = rtf(xc.x*mk.x + xp.x*(1.f-mk.x));
    o.y = rtf(xc.y*mk.y + xp.y*(1.f-mk.y));
    o.z = rtf(xc.z*mk.z + xp.z*(1.f-mk.z));
    o.w = rtf(xc.w*mk.w + xp.w*(1.f-mk.w));
    *(float4*)(g_xk + e) = o;

    o.x = rtf(xc.x*mv.x + xp.x*(1.f-mv.x));
    o.y = rtf(xc.y*mv.y + xp.y*(1.f-mv.y));
    o.z = rtf(xc.z*mv.z + xp.z*(1.f-mv.z));
    o.w = rtf(xc.w*mv.w + xp.w*(1.f-mv.w));
    *(float4*)(g_xv + e) = o;
}

// ---------------- TF32 mma.sync GEMM: C[M,N] = A[M,K] * W[N,K]^T -------------
// CTA 128x128, 4 warps (2x2), warp tile 64x64, BK=16, 3-stage cp.async,
// ldmatrix.x4 fragment loads. 3 CTAs/SM.
#define BMt 128
#define BNt 128
#define BKg 16
#define STR16 20                         // 16 floats + 4 pad
#define STG_A (BMt*STR16)                // 2560 words
#define STG_TOT (2*STG_A)                // 5120 words (A+B)
#define GSMEM (3*STG_TOT*4)              // 61440 bytes
#define NCHUNK (Dz/BKg)                  // 64

__device__ __forceinline__ void gemm_body(const float* __restrict__ A,
                                          const float* __restrict__ W,
                                          float* __restrict__ C,
                                          int sigmoid, float* smf)
{
    const int tid  = threadIdx.x;
    const int wid  = tid >> 5;
    const int lane = tid & 31;
    const int gp   = lane >> 2;
    const int tg   = lane & 3;
    const int wm   = (wid >> 1) * 64;
    const int wn   = (wid & 1) * 64;
    const int bm   = blockIdx.y * BMt;
    const int bn   = blockIdx.x * BNt;

    const float* Ag = A + (size_t)bm * Dz;
    const float* Wg = W + (size_t)bn * Dz;
    const uint32_t smb = smem_u32(smf);

    const int lrow = tid >> 2;          // 0..31
    const int lseg = tid & 3;           // 0..3
    const int rowSel = lane & 15;
    const int hi4 = (lane >> 4) << 2;   // 0 or 4 words

    auto issue = [&](int it) {
        int s = it % 3;
        uint32_t stA = smb + (uint32_t)(s * STG_TOT * 4);
        uint32_t stB = stA + STG_A * 4;
        int k0 = it * BKg;
        #pragma unroll
        for (int i = 0; i < 4; i++) {
            int r = lrow + 32 * i;
            uint32_t off = (uint32_t)(r * STR16 + lseg * 4) * 4;
            cp16(stA + off, Ag + (size_t)r * Dz + k0 + lseg * 4);
            cp16(stB + off, Wg + (size_t)r * Dz + k0 + lseg * 4);
        }
        CP_COMMIT();
    };

    float acc[4][8][4];
    #pragma unroll
    for (int mi = 0; mi < 4; mi++)
        #pragma unroll
        for (int ni = 0; ni < 8; ni++)
            #pragma unroll
            for (int q = 0; q < 4; q++) acc[mi][ni][q] = 0.f;

    issue(0);
    issue(1);

    #pragma unroll 1
    for (int it = 0; it < NCHUNK; it++) {
        if (it >= NCHUNK - 1) { CP_WAIT0(); } else { CP_WAIT1(); }
        __syncthreads();
        if (it + 2 < NCHUNK) issue(it + 2);

        uint32_t stA = smb + (uint32_t)((it % 3) * STG_TOT * 4);
        uint32_t stB = stA + STG_A * 4;

        #pragma unroll
        for (int ks = 0; ks < 2; ks++) {
            uint32_t a[4][4], b[4][4];
            const int cw = ks * 8 + hi4;
            #pragma unroll
            for (int mi = 0; mi < 4; mi++) {
                uint32_t ad = stA + (uint32_t)(((wm + mi*16 + rowSel) * STR16 + cw) * 4);
                ldsm4(a[mi][0], a[mi][1], a[mi][2], a[mi][3], ad);
            }
            #pragma unroll
            for (int p = 0; p < 4; p++) {
                uint32_t bd = stB + (uint32_t)(((wn + p*16 + rowSel) * STR16 + cw) * 4);
                ldsm4(b[p][0], b[p][1], b[p][2], b[p][3], bd);
            }
            #pragma unroll
            for (int mi = 0; mi < 4; mi++)
                #pragma unroll
                for (int p = 0; p < 4; p++) {
                    uint32_t b0[2] = { b[p][0], b[p][2] };   // ni = 2p
                    uint32_t b1[2] = { b[p][1], b[p][3] };   // ni = 2p+1
                    mma_tf32(acc[mi][2*p],     a[mi], b0);
                    mma_tf32(acc[mi][2*p + 1], a[mi], b1);
                }
        }
    }

    #pragma unroll
    for (int mi = 0; mi < 4; mi++) {
        int r0 = bm + wm + mi * 16 + gp;
        #pragma unroll
        for (int ni = 0; ni < 8; ni++) {
            int cc = bn + wn + ni * 8 + tg * 2;
            float v0 = acc[mi][ni][0], v1 = acc[mi][ni][1];
            float v2 = acc[mi][ni][2], v3 = acc[mi][ni][3];
            if (sigmoid) {
                v0 = 1.f/(1.f+__expf(-v0));
                v1 = 1.f/(1.f+__expf(-v1));
                v2 = 1.f/(1.f+__expf(-v2));
                v3 = 1.f/(1.f+__expf(-v3));
            }
            *(float2*)(C + (size_t)r0 * Dz + cc)       = make_float2(v0, v1);
            *(float2*)(C + (size_t)(r0 + 8) * Dz + cc) = make_float2(v2, v3);
        }
    }
}

// fused QKV: blockIdx.z selects (A, W, C, sigmoid)
__global__ void __launch_bounds__(128, 3)
gemm_qkv()
{
    extern __shared__ float smf[];
    int z = blockIdx.z;
    const float* A = (z == 0) ? g_xr : (z == 1) ? g_xk : g_xv;
    float*       C = (z == 0) ? g_r  : (z == 1) ? g_k  : g_v;
    gemm_body(A, g_W[z], C, z == 0, smf);
}

__global__ void __launch_bounds__(128, 3)
gemm_out(float* __restrict__ out)
{
    extern __shared__ float smf[];
    gemm_body(g_xr, g_W[3], out, 0, smf);
}

// ---------------- WKV chunked scan -------------------------------------------
__global__ void wkv_pass1(const float* __restrict__ tdecay)
{
    int b  = blockIdx.y;
    int ch = blockIdx.z;
    int c  = blockIdx.x * blockDim.x + threadIdx.x;

    float w = expf(-expf(tdecay[c]));
    size_t base = ((size_t)(b*Tz + ch*LCH))*Dz + c;
    const float* kp = g_k + base;
    const float* vp = g_v + base;

    float num = 0.f, den = 0.f;
    #pragma unroll 4
    for (int t = 0; t < LCH; t++) {
        float ek = __expf(kp[(size_t)t*Dz]);
        float vv = vp[(size_t)t*Dz];
        num = fmaf(ek, vv, num * w);
        den = fmaf(den, w, ek);
    }
    size_t idx = ((size_t)(b*NCH + ch)*Kz + c)*2;
    g_chunk[idx]   = num;
    g_chunk[idx+1] = den;
}

__global__ void wkv_pass2(const float* __restrict__ state,
                          const float* __restrict__ tdecay)
{
    int gid = blockIdx.x * blockDim.x + threadIdx.x;
    if (gid >= Bz*Kz) return;
    int b = gid >> 10;
    int c = gid & (Kz-1);

    float ed = expf(tdecay[c]);
    float wL = expf(-ed * (float)LCH);    // w^LCH exactly

    float num = state[(b*Kz + c)*3 + 0];
    float den = state[(b*Kz + c)*3 + 1];
    #pragma unroll
    for (int ch = 0; ch < NCH; ch++) {
        size_t idx = ((size_t)(b*NCH + ch)*Kz + c)*2;
        g_init[idx]   = num;
        g_init[idx+1] = den;
        num = fmaf(num, wL, g_chunk[idx]);
        den = fmaf(den, wL, g_chunk[idx+1]);
    }
}

__global__ void wkv_pass3(const float* __restrict__ tdecay,
                          const float* __restrict__ tfirst)
{
    int b  = blockIdx.y;
    int ch = blockIdx.z;
    int c  = blockIdx.x * blockDim.x + threadIdx.x;

    float w  = expf(-expf(tdecay[c]));
    float eu = expf(tfirst[c]);
    size_t idx = ((size_t)(b*NCH + ch)*Kz + c)*2;
    float num = g_init[idx];
    float den = g_init[idx+1];

    size_t base = ((size_t)(b*Tz + ch*LCH))*Dz + c;
    const float* kp = g_k   + base;
    const float* vp = g_v   + base;
    const float* rp = g_r   + base;
    float*       op = g_att + base;

    float s1 = 0.f, s2 = 0.f;
    #pragma unroll 4
    for (int t = 0; t < LCH; t++) {
        float kk = kp[(size_t)t*Dz];
        float vv = vp[(size_t)t*Dz];
        float rr = rp[(size_t)t*Dz];
        float ek = __expf(kk);
        float bonus = eu * ek;
        float wkv = __fdividef(fmaf(bonus, vv, num), den + bonus + 1e-9f);
        float att = rr * wkv;
        op[(size_t)t*Dz] = att;
        s1 += att;
        s2 = fmaf(att, att, s2);
        num = fmaf(ek, vv, num * w);
        den = fmaf(den, w, ek);
    }

    __shared__ float sh1[256], sh2[256];
    int tid = threadIdx.x;
    sh1[tid] = s1; sh2[tid] = s2;
    __syncthreads();
    for (int s = 128; s > 0; s >>= 1) {
        if (tid < s) { sh1[tid] += sh1[tid+s]; sh2[tid] += sh2[tid+s]; }
        __syncthreads();
    }
    if (tid == 0) {
        atomicAdd(&g_stats[2*b+0], sh1[0]);
        atomicAdd(&g_stats[2*b+1], sh2[0]);
    }
}

__global__ void finalize_kernel() {
    int b = threadIdx.x;
    if (b < Bz) {
        float n = (float)Tz * (float)Dz;
        float mean = g_stats[2*b] / n;
        float var  = g_stats[2*b+1] / n - mean*mean;
        g_mean[b] = mean;
        g_rstd[b] = rsqrtf(var + 1e-5f);
    }
}

__global__ void norm_kernel(const float* __restrict__ gamma, const float* __restrict__ beta)
{
    int idx = blockIdx.x * blockDim.x + threadIdx.x;
    long e = (long)idx * 4;
    if (e >= (long)BT*Dz) return;
    int d = (int)(e & (Dz-1));
    int b = (int)(e >> 21);
    float mean = g_mean[b], rstd = g_rstd[b];

    float4 a  = *(const float4*)(g_att + e);
    float4 gv = *(const float4*)(gamma + d);
    float4 bv = *(const float4*)(beta + d);
    float4 o;
    o.x = rtf((a.x - mean)*rstd*gv.x + bv.x);
    o.y = rtf((a.y - mean)*rstd*gv.y + bv.y);
    o.z = rtf((a.z - mean)*rstd*gv.z + bv.z);
    o.w = rtf((a.w - mean)*rstd*gv.w + bv.w);
    *(float4*)(g_xr + e) = o;
}

// ---------------- launcher ---------------------------------------------------
extern "C" void kernel_launch(void* const* d_in, const int* in_sizes, int n_in,
                              void* d_out, int out_size)
{
    const float* x      = (const float*)d_in[0];
    const float* state  = (const float*)d_in[1];
    const float* W_r    = (const float*)d_in[2];
    const float* W_k    = (const float*)d_in[3];
    const float* W_v    = (const float*)d_in[4];
    const float* W_o    = (const float*)d_in[5];
    const float* tmr    = (const float*)d_in[6];
    const float* tmk    = (const float*)d_in[7];
    const float* tmv    = (const float*)d_in[8];
    const float* tdecay = (const float*)d_in[9];
    const float* tfirst = (const float*)d_in[10];
    const float* gamma  = (const float*)d_in[11];
    const float* beta   = (const float*)d_in[12];
    float* out = (float*)d_out;

    cudaFuncSetAttribute(gemm_qkv, cudaFuncAttributeMaxDynamicSharedMemorySize, GSMEM);
    cudaFuncSetAttribute(gemm_out, cudaFuncAttributeMaxDynamicSharedMemorySize, GSMEM);

    zero_stats_kernel<<<1, 32>>>();
    round_w_kernel<<<dim3(Dz*Dz/4/256, 4), 256>>>(W_r, W_k, W_v, W_o);
    mix_kernel<<<(BT*Dz/4 + 255)/256, 256>>>(x, state, tmr, tmk, tmv);

    gemm_qkv<<<dim3(Dz/BNt, BT/BMt, 3), 128, GSMEM>>>();

    wkv_pass1<<<dim3(Kz/256, Bz, NCH), 256>>>(tdecay);
    wkv_pass2<<<Bz*Kz/256, 256>>>(state, tdecay);
    wkv_pass3<<<dim3(Kz/256, Bz, NCH), 256>>>(tdecay, tfirst);

    finalize_kernel<<<1, 32>>>();
    norm_kernel<<<(BT*Dz/4 + 255)/256, 256>>>(gamma, beta);

    gemm_out<<<dim3(Dz/BNt, BT/BMt), 128, GSMEM>>>(out);
}

// round 8
// speedup vs baseline: 1.0578x; 1.0578x over previous
#include <cuda_runtime.h>
#include <cstdint>

#define Bz 8
#define Tz 2048
#define Dz 1024
#define Kz 1024
#define BT (Bz*Tz)
#define NCH 8
#define LCH (Tz/NCH)     // 256

// ---------------- scratch (device globals; no allocations allowed) ----------
__device__ float g_xr[BT*Dz];
__device__ float g_xk[BT*Dz];
__device__ float g_xv[BT*Dz];
__device__ float g_r [BT*Dz];
__device__ float g_k [BT*Dz];
__device__ float g_v [BT*Dz];
__device__ float g_att[BT*Dz];
__device__ float g_W[4][Dz*Dz];          // tf32-rounded W_r,W_k,W_v,W_o
__device__ float g_chunk[Bz*NCH*Kz*2];
__device__ float g_init [Bz*NCH*Kz*2];
__device__ float g_stats[2*Bz];
__device__ float g_mean[Bz];
__device__ float g_rstd[Bz];

// ---------------- helpers ----------------------------------------------------
__device__ __forceinline__ float rtf(float x) {
    uint32_t r;
    asm("cvt.rna.tf32.f32 %0, %1;" : "=r"(r) : "f"(x));
    return __uint_as_float(r);
}
__device__ __forceinline__ void cp16(uint32_t saddr, const void* g) {
    asm volatile("cp.async.cg.shared.global [%0], [%1], 16;" :: "r"(saddr), "l"(g) : "memory");
}
#define CP_COMMIT() asm volatile("cp.async.commit_group;" ::: "memory")
#define CP_WAIT1()  asm volatile("cp.async.wait_group 1;" ::: "memory")
#define CP_WAIT0()  asm volatile("cp.async.wait_group 0;" ::: "memory")

__device__ __forceinline__ uint32_t smem_u32(const void* p) {
    uint32_t a;
    asm("{ .reg .u64 t; cvta.to.shared.u64 t, %1; cvt.u32.u64 %0, t; }" : "=r"(a) : "l"(p));
    return a;
}
__device__ __forceinline__ void mma_tf32s(float* d, uint32_t a0, uint32_t a1, uint32_t a2,
                                          uint32_t a3, uint32_t b0, uint32_t b1) {
    asm volatile(
        "mma.sync.aligned.m16n8k8.row.col.f32.tf32.tf32.f32 "
        "{%0,%1,%2,%3}, {%4,%5,%6,%7}, {%8,%9}, {%0,%1,%2,%3};"
        : "+f"(d[0]), "+f"(d[1]), "+f"(d[2]), "+f"(d[3])
        : "r"(a0), "r"(a1), "r"(a2), "r"(a3), "r"(b0), "r"(b1));
}
__device__ __forceinline__ void ldsm4(uint32_t& r0, uint32_t& r1, uint32_t& r2, uint32_t& r3,
                                      uint32_t addr) {
    asm volatile("ldmatrix.sync.aligned.m8n8.x4.shared.b16 {%0,%1,%2,%3}, [%4];"
                 : "=r"(r0), "=r"(r1), "=r"(r2), "=r"(r3) : "r"(addr));
}

// ---------------- small kernels ----------------------------------------------
__global__ void zero_stats_kernel() {
    int i = threadIdx.x;
    if (i < 2*Bz) g_stats[i] = 0.f;
}

__global__ void round_w_kernel(const float* __restrict__ w0, const float* __restrict__ w1,
                               const float* __restrict__ w2, const float* __restrict__ w3)
{
    int m = blockIdx.y;
    const float* s = (m == 0) ? w0 : (m == 1) ? w1 : (m == 2) ? w2 : w3;
    long e = ((long)blockIdx.x * blockDim.x + threadIdx.x) * 4;
    if (e >= (long)Dz*Dz) return;
    float4 v = *(const float4*)(s + e);
    v.x = rtf(v.x); v.y = rtf(v.y); v.z = rtf(v.z); v.w = rtf(v.w);
    *(float4*)(&g_W[m][0] + e) = v;
}

__global__ void mix_kernel(const float* __restrict__ x,
                           const float* __restrict__ state,
                           const float* __restrict__ tmr,
                           const float* __restrict__ tmk,
                           const float* __restrict__ tmv)
{
    int idx = blockIdx.x * blockDim.x + threadIdx.x;
    long e = (long)idx * 4;
    if (e >= (long)BT*Dz) return;
    int d  = (int)(e & (Dz-1));
    int bt = (int)(e >> 10);
    int t  = bt & (Tz-1);
    int b  = bt >> 11;

    float4 xc = *(const float4*)(x + e);
    float4 xp;
    if (t == 0) {
        xp.x = state[(b*Kz + d + 0)*3 + 2];
        xp.y = state[(b*Kz + d + 1)*3 + 2];
        xp.z = state[(b*Kz + d + 2)*3 + 2];
        xp.w = state[(b*Kz + d + 3)*3 + 2];
    } else {
        xp = *(const float4*)(x + e - Dz);
    }
    float4 mr = *(const float4*)(tmr + d);
    float4 mk = *(const float4*)(tmk + d);
    float4 mv = *(const float4*)(tmv + d);

    float4 o;
    o.x = rtf(xc.x*mr.x + xp.x*(1.f-mr.x));
    o.y = rtf(xc.y*mr.y + xp.y*(1.f-mr.y));
    o.z = rtf(xc.z*mr.z + xp.z*(1.f-mr.z));
    o.w = rtf(xc.w*mr.w + xp.w*(1.f-mr.w));
    *(float4*)(g_xr + e) = o;

    o.x = rtf(xc.x*mk.x + xp.x*(1.f-mk.x));
    o.y = rtf(xc.y*mk.y + xp.y*(1.f-mk.y));
    o.z = rtf(xc.z*mk.z + xp.z*(1.f-mk.z));
    o.w = rtf(xc.w*mk.w + xp.w*(1.f-mk.w));
    *(float4*)(g_xk + e) = o;

    o.x = rtf(xc.x*mv.x + xp.x*(1.f-mv.x));
    o.y = rtf(xc.y*mv.y + xp.y*(1.f-mv.y));
    o.z = rtf(xc.z*mv.z + xp.z*(1.f-mv.z));
    o.w = rtf(xc.w*mv.w + xp.w*(1.f-mv.w));
    *(float4*)(g_xv + e) = o;
}

// ---------------- TF32 mma.sync GEMM: C[M,N] = A[M,K] * W[N,K]^T -------------
// CTA 128x128, 4 warps (2x2), warp tile 64x64, BK=32, 2-stage cp.async,
// ldmatrix.x4 fragment loads with constant offsets. 3 CTAs/SM.
#define BMt 128
#define BNt 128
#define BKg 32
#define STRIDEW 36
#define STG_A (BMt*STRIDEW)
#define STG_B (BNt*STRIDEW)
#define STG_TOT (STG_A+STG_B)
#define GSMEM (2*STG_TOT*4)              // 73728 bytes
#define NCHUNK (Dz/BKg)                  // 32

__device__ __forceinline__ void gemm_body(const float* __restrict__ A,
                                          const float* __restrict__ W,
                                          float* __restrict__ C,
                                          int sigmoid, float* smf)
{
    const int tid  = threadIdx.x;
    const int wid  = tid >> 5;
    const int lane = tid & 31;
    const int gp   = lane >> 2;
    const int tg   = lane & 3;
    const int wm   = (wid >> 1) * 64;
    const int wn   = (wid & 1) * 64;
    const int bm   = blockIdx.y * BMt;
    const int bn   = blockIdx.x * BNt;

    const float* Ag = A + (size_t)bm * Dz;
    const float* Wg = W + (size_t)bn * Dz;
    const uint32_t smb = smem_u32(smf);

    const int lrow = tid >> 3;          // 0..15
    const int lseg = tid & 7;           // 0..7
    const int rowSel = lane & 15;
    const int hi4 = (lane >> 4) << 2;   // 0 or 4 words

    // ldmatrix base addresses (stage 0); stage 1 = + STG_TOT*4
    const uint32_t aBase = smb + (uint32_t)(((wm + rowSel) * STRIDEW + hi4) * 4);
    const uint32_t bBase = smb + (uint32_t)(STG_A * 4)
                         + (uint32_t)(((wn + rowSel) * STRIDEW + hi4) * 4);

    auto issue = [&](int it) {
        uint32_t stA = smb + (uint32_t)((it & 1) * STG_TOT * 4);
        uint32_t stB = stA + STG_A * 4;
        int k0 = it * BKg;
        #pragma unroll
        for (int i = 0; i < 8; i++) {
            int r = lrow + 16 * i;
            uint32_t off = (uint32_t)(r * STRIDEW + lseg * 4) * 4;
            cp16(stA + off, Ag + (size_t)r * Dz + k0 + lseg * 4);
            cp16(stB + off, Wg + (size_t)r * Dz + k0 + lseg * 4);
        }
        CP_COMMIT();
    };

    float acc[4][8][4];
    #pragma unroll
    for (int mi = 0; mi < 4; mi++)
        #pragma unroll
        for (int ni = 0; ni < 8; ni++)
            #pragma unroll
            for (int q = 0; q < 4; q++) acc[mi][ni][q] = 0.f;

    auto compute = [&](uint32_t sOff) {
        const uint32_t aB = aBase + sOff;
        const uint32_t bB = bBase + sOff;
        #pragma unroll
        for (int ks = 0; ks < 4; ks++) {
            uint32_t a[4][4], b[4][4];
            #pragma unroll
            for (int mi = 0; mi < 4; mi++)
                ldsm4(a[mi][0], a[mi][1], a[mi][2], a[mi][3],
                      aB + (uint32_t)(mi * 16 * STRIDEW * 4 + ks * 32));
            #pragma unroll
            for (int p = 0; p < 4; p++)
                ldsm4(b[p][0], b[p][1], b[p][2], b[p][3],
                      bB + (uint32_t)(p * 16 * STRIDEW * 4 + ks * 32));
            #pragma unroll
            for (int mi = 0; mi < 4; mi++)
                #pragma unroll
                for (int p = 0; p < 4; p++) {
                    mma_tf32s(acc[mi][2*p],   a[mi][0], a[mi][1], a[mi][2], a[mi][3],
                              b[p][0], b[p][2]);
                    mma_tf32s(acc[mi][2*p+1], a[mi][0], a[mi][1], a[mi][2], a[mi][3],
                              b[p][1], b[p][3]);
                }
        }
    };

    issue(0);
    issue(1);

    #pragma unroll 1
    for (int it = 0; it < NCHUNK; it += 2) {
        // ---- phase 0: compute stage 0 (chunk it) ----
        CP_WAIT1();
        __syncthreads();
        compute(0);
        __syncthreads();
        if (it + 2 < NCHUNK) issue(it + 2);
        // ---- phase 1: compute stage 1 (chunk it+1) ----
        if (it + 3 < NCHUNK) { CP_WAIT1(); } else { CP_WAIT0(); }
        __syncthreads();
        compute((uint32_t)(STG_TOT * 4));
        __syncthreads();
        if (it + 3 < NCHUNK) issue(it + 3);
    }

    #pragma unroll
    for (int mi = 0; mi < 4; mi++) {
        int r0 = bm + wm + mi * 16 + gp;
        #pragma unroll
        for (int ni = 0; ni < 8; ni++) {
            int cc = bn + wn + ni * 8 + tg * 2;
            float v0 = acc[mi][ni][0], v1 = acc[mi][ni][1];
            float v2 = acc[mi][ni][2], v3 = acc[mi][ni][3];
            if (sigmoid) {
                v0 = 1.f/(1.f+__expf(-v0));
                v1 = 1.f/(1.f+__expf(-v1));
                v2 = 1.f/(1.f+__expf(-v2));
                v3 = 1.f/(1.f+__expf(-v3));
            }
            *(float2*)(C + (size_t)r0 * Dz + cc)       = make_float2(v0, v1);
            *(float2*)(C + (size_t)(r0 + 8) * Dz + cc) = make_float2(v2, v3);
        }
    }
}

// fused QKV: blockIdx.z selects (A, W, C, sigmoid)
__global__ void __launch_bounds__(128, 3)
gemm_qkv()
{
    extern __shared__ float smf[];
    int z = blockIdx.z;
    const float* A = (z == 0) ? g_xr : (z == 1) ? g_xk : g_xv;
    float*       C = (z == 0) ? g_r  : (z == 1) ? g_k  : g_v;
    gemm_body(A, g_W[z], C, z == 0, smf);
}

__global__ void __launch_bounds__(128, 3)
gemm_out(float* __restrict__ out)
{
    extern __shared__ float smf[];
    gemm_body(g_xr, g_W[3], out, 0, smf);
}

// ---------------- WKV chunked scan -------------------------------------------
__global__ void wkv_pass1(const float* __restrict__ tdecay)
{
    int b  = blockIdx.y;
    int ch = blockIdx.z;
    int c  = blockIdx.x * blockDim.x + threadIdx.x;

    float w = expf(-expf(tdecay[c]));
    size_t base = ((size_t)(b*Tz + ch*LCH))*Dz + c;
    const float* kp = g_k + base;
    const float* vp = g_v + base;

    float num = 0.f, den = 0.f;
    #pragma unroll 4
    for (int t = 0; t < LCH; t++) {
        float ek = __expf(kp[(size_t)t*Dz]);
        float vv = vp[(size_t)t*Dz];
        num = fmaf(ek, vv, num * w);
        den = fmaf(den, w, ek);
    }
    size_t idx = ((size_t)(b*NCH + ch)*Kz + c)*2;
    g_chunk[idx]   = num;
    g_chunk[idx+1] = den;
}

__global__ void wkv_pass2(const float* __restrict__ state,
                          const float* __restrict__ tdecay)
{
    int gid = blockIdx.x * blockDim.x + threadIdx.x;
    if (gid >= Bz*Kz) return;
    int b = gid >> 10;
    int c = gid & (Kz-1);

    float ed = expf(tdecay[c]);
    float wL = expf(-ed * (float)LCH);    // w^LCH exactly

    float num = state[(b*Kz + c)*3 + 0];
    float den = state[(b*Kz + c)*3 + 1];
    #pragma unroll
    for (int ch = 0; ch < NCH; ch++) {
        size_t idx = ((size_t)(b*NCH + ch)*Kz + c)*2;
        g_init[idx]   = num;
        g_init[idx+1] = den;
        num = fmaf(num, wL, g_chunk[idx]);
        den = fmaf(den, wL, g_chunk[idx+1]);
    }
}

__global__ void wkv_pass3(const float* __restrict__ tdecay,
                          const float* __restrict__ tfirst)
{
    int b  = blockIdx.y;
    int ch = blockIdx.z;
    int c  = blockIdx.x * blockDim.x + threadIdx.x;

    float w  = expf(-expf(tdecay[c]));
    float eu = expf(tfirst[c]);
    size_t idx = ((size_t)(b*NCH + ch)*Kz + c)*2;
    float num = g_init[idx];
    float den = g_init[idx+1];

    size_t base = ((size_t)(b*Tz + ch*LCH))*Dz + c;
    const float* kp = g_k   + base;
    const float* vp = g_v   + base;
    const float* rp = g_r   + base;
    float*       op = g_att + base;

    float s1 = 0.f, s2 = 0.f;
    #pragma unroll 4
    for (int t = 0; t < LCH; t++) {
        float kk = kp[(size_t)t*Dz];
        float vv = vp[(size_t)t*Dz];
        float rr = rp[(size_t)t*Dz];
        float ek = __expf(kk);
        float bonus = eu * ek;
        float wkv = __fdividef(fmaf(bonus, vv, num), den + bonus + 1e-9f);
        float att = rr * wkv;
        op[(size_t)t*Dz] = att;
        s1 += att;
        s2 = fmaf(att, att, s2);
        num = fmaf(ek, vv, num * w);
        den = fmaf(den, w, ek);
    }

    __shared__ float sh1[256], sh2[256];
    int tid = threadIdx.x;
    sh1[tid] = s1; sh2[tid] = s2;
    __syncthreads();
    for (int s = 128; s > 0; s >>= 1) {
        if (tid < s) { sh1[tid] += sh1[tid+s]; sh2[tid] += sh2[tid+s]; }
        __syncthreads();
    }
    if (tid == 0) {
        atomicAdd(&g_stats[2*b+0], sh1[0]);
        atomicAdd(&g_stats[2*b+1], sh2[0]);
    }
}

__global__ void finalize_kernel() {
    int b = threadIdx.x;
    if (b < Bz) {
        float n = (float)Tz * (float)Dz;
        float mean = g_stats[2*b] / n;
        float var  = g_stats[2*b+1] / n - mean*mean;
        g_mean[b] = mean;
        g_rstd[b] = rsqrtf(var + 1e-5f);
    }
}

__global__ void norm_kernel(const float* __restrict__ gamma, const float* __restrict__ beta)
{
    int idx = blockIdx.x * blockDim.x + threadIdx.x;
    long e = (long)idx * 4;
    if (e >= (long)BT*Dz) return;
    int d = (int)(e & (Dz-1));
    int b = (int)(e >> 21);
    float mean = g_mean[b], rstd = g_rstd[b];

    float4 a  = *(const float4*)(g_att + e);
    float4 gv = *(const float4*)(gamma + d);
    float4 bv = *(const float4*)(beta + d);
    float4 o;
    o.x = rtf((a.x - mean)*rstd*gv.x + bv.x);
    o.y = rtf((a.y - mean)*rstd*gv.y + bv.y);
    o.z = rtf((a.z - mean)*rstd*gv.z + bv.z);
    o.w = rtf((a.w - mean)*rstd*gv.w + bv.w);
    *(float4*)(g_xr + e) = o;
}

// ---------------- launcher ---------------------------------------------------
extern "C" void kernel_launch(void* const* d_in, const int* in_sizes, int n_in,
                              void* d_out, int out_size)
{
    const float* x      = (const float*)d_in[0];
    const float* state  = (const float*)d_in[1];
    const float* W_r    = (const float*)d_in[2];
    const float* W_k    = (const float*)d_in[3];
    const float* W_v    = (const float*)d_in[4];
    const float* W_o    = (const float*)d_in[5];
    const float* tmr    = (const float*)d_in[6];
    const float* tmk    = (const float*)d_in[7];
    const float* tmv    = (const float*)d_in[8];
    const float* tdecay = (const float*)d_in[9];
    const float* tfirst = (const float*)d_in[10];
    const float* gamma  = (const float*)d_in[11];
    const float* beta   = (const float*)d_in[12];
    float* out = (float*)d_out;

    cudaFuncSetAttribute(gemm_qkv, cudaFuncAttributeMaxDynamicSharedMemorySize, GSMEM);
    cudaFuncSetAttribute(gemm_out, cudaFuncAttributeMaxDynamicSharedMemorySize, GSMEM);

    zero_stats_kernel<<<1, 32>>>();
    round_w_kernel<<<dim3(Dz*Dz/4/256, 4), 256>>>(W_r, W_k, W_v, W_o);
    mix_kernel<<<(BT*Dz/4 + 255)/256, 256>>>(x, state, tmr, tmk, tmv);

    gemm_qkv<<<dim3(Dz/BNt, BT/BMt, 3), 128, GSMEM>>>();

    wkv_pass1<<<dim3(Kz/256, Bz, NCH), 256>>>(tdecay);
    wkv_pass2<<<Bz*Kz/256, 256>>>(state, tdecay);
    wkv_pass3<<<dim3(Kz/256, Bz, NCH), 256>>>(tdecay, tfirst);

    finalize_kernel<<<1, 32>>>();
    norm_kernel<<<(BT*Dz/4 + 255)/256, 256>>>(gamma, beta);

    gemm_out<<<dim3(Dz/BNt, BT/BMt), 128, GSMEM>>>(out);
}

// round 9
// speedup vs baseline: 1.2778x; 1.2080x over previous
#include <cuda_runtime.h>
#include <cstdint>

#define Bz 8
#define Tz 2048
#define Dz 1024
#define Kz 1024
#define BT (Bz*Tz)
#define NCH 16
#define LCH (Tz/NCH)     // 128

// ---------------- scratch (device globals; no allocations allowed) ----------
__device__ float g_xr[BT*Dz];
__device__ float g_xk[BT*Dz];
__device__ float g_xv[BT*Dz];
__device__ float g_r [BT*Dz];
__device__ float g_k [BT*Dz];
__device__ float g_v [BT*Dz];
__device__ float g_att[BT*Dz];
__device__ float g_W[4][Dz*Dz];          // tf32 W_r,W_k,W_v, (W_o*gamma)
__device__ float g_chunk[Bz*NCH*Kz*2];
__device__ float g_v1[Dz];
__device__ float g_v2[Dz];
__device__ float g_stats[2*Bz];
__device__ float g_mean[Bz];
__device__ float g_rstd[Bz];

// ---------------- helpers ----------------------------------------------------
__device__ __forceinline__ float rtf(float x) {
    uint32_t r;
    asm("cvt.rna.tf32.f32 %0, %1;" : "=r"(r) : "f"(x));
    return __uint_as_float(r);
}
__device__ __forceinline__ void cp16(uint32_t saddr, const void* g) {
    asm volatile("cp.async.cg.shared.global [%0], [%1], 16;" :: "r"(saddr), "l"(g) : "memory");
}
#define CP_COMMIT() asm volatile("cp.async.commit_group;" ::: "memory")
#define CP_WAIT1()  asm volatile("cp.async.wait_group 1;" ::: "memory")
#define CP_WAIT0()  asm volatile("cp.async.wait_group 0;" ::: "memory")

__device__ __forceinline__ uint32_t smem_u32(const void* p) {
    uint32_t a;
    asm("{ .reg .u64 t; cvta.to.shared.u64 t, %1; cvt.u32.u64 %0, t; }" : "=r"(a) : "l"(p));
    return a;
}
__device__ __forceinline__ void mma_tf32(float* d, const uint32_t* a, const uint32_t* b) {
    asm volatile(
        "mma.sync.aligned.m16n8k8.row.col.f32.tf32.tf32.f32 "
        "{%0,%1,%2,%3}, {%4,%5,%6,%7}, {%8,%9}, {%0,%1,%2,%3};"
        : "+f"(d[0]), "+f"(d[1]), "+f"(d[2]), "+f"(d[3])
        : "r"(a[0]), "r"(a[1]), "r"(a[2]), "r"(a[3]), "r"(b[0]), "r"(b[1]));
}

// ---------------- small kernels ----------------------------------------------
__global__ void zero_stats_kernel() {
    int i = threadIdx.x;
    if (i < 2*Bz) g_stats[i] = 0.f;
}

// tf32-round weights; m==3 bakes gamma into W_o columns
__global__ void round_w_kernel(const float* __restrict__ w0, const float* __restrict__ w1,
                               const float* __restrict__ w2, const float* __restrict__ w3,
                               const float* __restrict__ gamma)
{
    int m = blockIdx.y;
    const float* s = (m == 0) ? w0 : (m == 1) ? w1 : (m == 2) ? w2 : w3;
    long e = ((long)blockIdx.x * blockDim.x + threadIdx.x) * 4;
    if (e >= (long)Dz*Dz) return;
    float4 v = *(const float4*)(s + e);
    if (m == 3) {
        int d = (int)(e & (Dz-1));
        float4 gv = *(const float4*)(gamma + d);
        v.x *= gv.x; v.y *= gv.y; v.z *= gv.z; v.w *= gv.w;
    }
    v.x = rtf(v.x); v.y = rtf(v.y); v.z = rtf(v.z); v.w = rtf(v.w);
    *(float4*)(&g_W[m][0] + e) = v;
}

// v1[n] = sum_d gamma[d]*Wo[n,d];  v2[n] = sum_d beta[d]*Wo[n,d]
// one warp per output row n (coalesced d per lane)
__global__ void v12_kernel(const float* __restrict__ Wo,
                           const float* __restrict__ gamma,
                           const float* __restrict__ beta)
{
    int wid  = threadIdx.x >> 5;
    int lane = threadIdx.x & 31;
    int n = blockIdx.x * 4 + wid;
    const float* wp = Wo + (size_t)n * Dz;
    float s1 = 0.f, s2 = 0.f;
    for (int d = lane; d < Dz; d += 32) {
        float wv = wp[d];
        s1 = fmaf(gamma[d], wv, s1);
        s2 = fmaf(beta[d],  wv, s2);
    }
    #pragma unroll
    for (int o = 16; o > 0; o >>= 1) {
        s1 += __shfl_xor_sync(0xffffffff, s1, o);
        s2 += __shfl_xor_sync(0xffffffff, s2, o);
    }
    if (lane == 0) { g_v1[n] = s1; g_v2[n] = s2; }
}

__global__ void mix_kernel(const float* __restrict__ x,
                           const float* __restrict__ state,
                           const float* __restrict__ tmr,
                           const float* __restrict__ tmk,
                           const float* __restrict__ tmv)
{
    int idx = blockIdx.x * blockDim.x + threadIdx.x;
    long e = (long)idx * 4;
    if (e >= (long)BT*Dz) return;
    int d  = (int)(e & (Dz-1));
    int bt = (int)(e >> 10);
    int t  = bt & (Tz-1);
    int b  = bt >> 11;

    float4 xc = *(const float4*)(x + e);
    float4 xp;
    if (t == 0) {
        xp.x = state[(b*Kz + d + 0)*3 + 2];
        xp.y = state[(b*Kz + d + 1)*3 + 2];
        xp.z = state[(b*Kz + d + 2)*3 + 2];
        xp.w = state[(b*Kz + d + 3)*3 + 2];
    } else {
        xp = *(const float4*)(x + e - Dz);
    }
    float4 mr = *(const float4*)(tmr + d);
    float4 mk = *(const float4*)(tmk + d);
    float4 mv = *(const float4*)(tmv + d);

    float4 o;
    o.x = rtf(xc.x*mr.x + xp.x*(1.f-mr.x));
    o.y = rtf(xc.y*mr.y + xp.y*(1.f-mr.y));
    o.z = rtf(xc.z*mr.z + xp.z*(1.f-mr.z));
    o.w = rtf(xc.w*mr.w + xp.w*(1.f-mr.w));
    *(float4*)(g_xr + e) = o;

    o.x = rtf(xc.x*mk.x + xp.x*(1.f-mk.x));
    o.y = rtf(xc.y*mk.y + xp.y*(1.f-mk.y));
    o.z = rtf(xc.z*mk.z + xp.z*(1.f-mk.z));
    o.w = rtf(xc.w*mk.w + xp.w*(1.f-mk.w));
    *(float4*)(g_xk + e) = o;

    o.x = rtf(xc.x*mv.x + xp.x*(1.f-mv.x));
    o.y = rtf(xc.y*mv.y + xp.y*(1.f-mv.y));
    o.z = rtf(xc.z*mv.z + xp.z*(1.f-mv.z));
    o.w = rtf(xc.w*mv.w + xp.w*(1.f-mv.w));
    *(float4*)(g_xv + e) = o;
}

// ---------------- TF32 mma.sync GEMM: C[M,N] = A[M,K] * W[N,K]^T -------------
// R6-proven core: CTA 128x128, 4 warps (2x2), warp tile 64x64, BK=32,
// 2-stage cp.async, scalar LDS fragment loads. 3 CTAs/SM.
// mode 0: plain. mode 1: sigmoid. mode 2: GroupNorm epilogue
//   out = rstd*acc + (v2[n] - rstd*mean*v1[n]).
#define BMt 128
#define BNt 128
#define BKg 32
#define STRIDEW 36
#define STG_A (BMt*STRIDEW)
#define STG_B (BNt*STRIDEW)
#define STG_TOT (STG_A+STG_B)
#define GSMEM (2*STG_TOT*4)              // 73728 bytes
#define NCHUNK (Dz/BKg)                  // 32

__device__ __forceinline__ void gemm_body(const float* __restrict__ A,
                                          const float* __restrict__ W,
                                          float* __restrict__ C,
                                          int mode, float* smf)
{
    const int tid  = threadIdx.x;
    const int wid  = tid >> 5;
    const int lane = tid & 31;
    const int gp   = lane >> 2;
    const int tg   = lane & 3;
    const int wm   = (wid >> 1) * 64;
    const int wn   = (wid & 1) * 64;
    const int bm   = blockIdx.y * BMt;
    const int bn   = blockIdx.x * BNt;

    const float* Ag = A + (size_t)bm * Dz;
    const float* Wg = W + (size_t)bn * Dz;
    const uint32_t smb = smem_u32(smf);

    const int lrow = tid >> 3;   // 0..15
    const int lseg = tid & 7;    // 0..7

    auto issue = [&](int it) {
        uint32_t stA = smb + (uint32_t)((it & 1) * STG_TOT * 4);
        uint32_t stB = stA + STG_A * 4;
        int k0 = it * BKg;
        #pragma unroll
        for (int i = 0; i < 8; i++) {
            int r = lrow + 16 * i;
            uint32_t off = (uint32_t)(r * STRIDEW + lseg * 4) * 4;
            cp16(stA + off, Ag + (size_t)r * Dz + k0 + lseg * 4);
            cp16(stB + off, Wg + (size_t)r * Dz + k0 + lseg * 4);
        }
        CP_COMMIT();
    };

    float acc[4][8][4];
    #pragma unroll
    for (int mi = 0; mi < 4; mi++)
        #pragma unroll
        for (int ni = 0; ni < 8; ni++)
            #pragma unroll
            for (int q = 0; q < 4; q++) acc[mi][ni][q] = 0.f;

    issue(0);
    issue(1);

    #pragma unroll 1
    for (int it = 0; it < NCHUNK; it++) {
        if (it == NCHUNK - 1) { CP_WAIT0(); } else { CP_WAIT1(); }
        __syncthreads();

        const float* stA = smf + (it & 1) * STG_TOT;
        const float* stB = stA + STG_A;

        #pragma unroll
        for (int ks = 0; ks < 4; ks++) {
            uint32_t a[4][4], b[8][2];
            const int c = ks * 8 + tg;
            #pragma unroll
            for (int mi = 0; mi < 4; mi++) {
                int r = wm + mi * 16 + gp;
                a[mi][0] = __float_as_uint(stA[r * STRIDEW + c]);
                a[mi][1] = __float_as_uint(stA[(r + 8) * STRIDEW + c]);
                a[mi][2] = __float_as_uint(stA[r * STRIDEW + c + 4]);
                a[mi][3] = __float_as_uint(stA[(r + 8) * STRIDEW + c + 4]);
            }
            #pragma unroll
            for (int ni = 0; ni < 8; ni++) {
                int n = wn + ni * 8 + gp;
                b[ni][0] = __float_as_uint(stB[n * STRIDEW + c]);
                b[ni][1] = __float_as_uint(stB[n * STRIDEW + c + 4]);
            }
            #pragma unroll
            for (int mi = 0; mi < 4; mi++)
                #pragma unroll
                for (int ni = 0; ni < 8; ni++)
                    mma_tf32(acc[mi][ni], a[mi], b[ni]);
        }
        __syncthreads();
        if (it + 2 < NCHUNK) issue(it + 2);
    }

    float rstd = 1.f, nmean = 0.f;
    if (mode == 2) {
        int bb = blockIdx.y >> 4;        // 16 CTAs of 128 rows per batch
        rstd  = g_rstd[bb];
        nmean = rstd * g_mean[bb];
    }

    #pragma unroll
    for (int mi = 0; mi < 4; mi++) {
        int r0 = bm + wm + mi * 16 + gp;
        #pragma unroll
        for (int ni = 0; ni < 8; ni++) {
            int cc = bn + wn + ni * 8 + tg * 2;
            float v0 = acc[mi][ni][0], v1 = acc[mi][ni][1];
            float v2 = acc[mi][ni][2], v3 = acc[mi][ni][3];
            if (mode == 1) {
                v0 = 1.f/(1.f+__expf(-v0));
                v1 = 1.f/(1.f+__expf(-v1));
                v2 = 1.f/(1.f+__expf(-v2));
                v3 = 1.f/(1.f+__expf(-v3));
            } else if (mode == 2) {
                float c0a = g_v2[cc]   - nmean * g_v1[cc];
                float c0b = g_v2[cc+1] - nmean * g_v1[cc+1];
                v0 = fmaf(rstd, v0, c0a);
                v1 = fmaf(rstd, v1, c0b);
                v2 = fmaf(rstd, v2, c0a);
                v3 = fmaf(rstd, v3, c0b);
            }
            *(float2*)(C + (size_t)r0 * Dz + cc)       = make_float2(v0, v1);
            *(float2*)(C + (size_t)(r0 + 8) * Dz + cc) = make_float2(v2, v3);
        }
    }
}

// fused QKV: blockIdx.z selects (A, W, C, mode)
__global__ void __launch_bounds__(128, 3)
gemm_qkv()
{
    extern __shared__ float smf[];
    int z = blockIdx.z;
    const float* A = (z == 0) ? g_xr : (z == 1) ? g_xk : g_xv;
    float*       C = (z == 0) ? g_r  : (z == 1) ? g_k  : g_v;
    gemm_body(A, g_W[z], C, (z == 0) ? 1 : 0, smf);
}

__global__ void __launch_bounds__(128, 3)
gemm_out(float* __restrict__ out)
{
    extern __shared__ float smf[];
    gemm_body(g_att, g_W[3], out, 2, smf);
}

// ---------------- WKV chunked scan -------------------------------------------
// pass 1: per-chunk (num,den) reduction. grid (Kz/256, Bz, NCH)
__global__ void wkv_pass1(const float* __restrict__ tdecay)
{
    int b  = blockIdx.y;
    int ch = blockIdx.z;
    int c  = blockIdx.x * blockDim.x + threadIdx.x;

    float w = expf(-expf(tdecay[c]));
    size_t base = ((size_t)(b*Tz + ch*LCH))*Dz + c;
    const float* kp = g_k + base;
    const float* vp = g_v + base;

    float num = 0.f, den = 0.f;
    #pragma unroll 4
    for (int t = 0; t < LCH; t++) {
        float ek = __expf(kp[(size_t)t*Dz]);
        float vv = vp[(size_t)t*Dz];
        num = fmaf(ek, vv, num * w);
        den = fmaf(den, w, ek);
    }
    size_t idx = ((size_t)(b*NCH + ch)*Kz + c)*2;
    g_chunk[idx]   = num;
    g_chunk[idx+1] = den;
}

// pass 3: combine predecessor chunk states, scan, write rtf(att) + GN stats
__global__ void wkv_pass3(const float* __restrict__ state,
                          const float* __restrict__ tdecay,
                          const float* __restrict__ tfirst)
{
    int b  = blockIdx.y;
    int ch = blockIdx.z;
    int c  = blockIdx.x * blockDim.x + threadIdx.x;

    float ed = expf(tdecay[c]);
    float w  = expf(-ed);
    float wL = expf(-ed * (float)LCH);   // w^LCH exactly
    float eu = expf(tfirst[c]);

    // incoming state for this chunk = fold of chunks 0..ch-1 over initial state
    float num = state[(b*Kz + c)*3 + 0];
    float den = state[(b*Kz + c)*3 + 1];
    for (int j = 0; j < ch; j++) {
        size_t cidx = ((size_t)(b*NCH + j)*Kz + c)*2;
        num = fmaf(num, wL, g_chunk[cidx]);
        den = fmaf(den, wL, g_chunk[cidx+1]);
    }

    size_t base = ((size_t)(b*Tz + ch*LCH))*Dz + c;
    const float* kp = g_k   + base;
    const float* vp = g_v   + base;
    const float* rp = g_r   + base;
    float*       op = g_att + base;

    float s1 = 0.f, s2 = 0.f;
    #pragma unroll 4
    for (int t = 0; t < LCH; t++) {
        float kk = kp[(size_t)t*Dz];
        float vv = vp[(size_t)t*Dz];
        float rr = rp[(size_t)t*Dz];
        float ek = __expf(kk);
        float bonus = eu * ek;
        float wkv = __fdividef(fmaf(bonus, vv, num), den + bonus + 1e-9f);
        float att = rtf(rr * wkv);       // tf32-ready for the W_o GEMM
        op[(size_t)t*Dz] = att;
        s1 += att;
        s2 = fmaf(att, att, s2);
        num = fmaf(ek, vv, num * w);
        den = fmaf(den, w, ek);
    }

    __shared__ float sh1[256], sh2[256];
    int tid = threadIdx.x;
    sh1[tid] = s1; sh2[tid] = s2;
    __syncthreads();
    for (int s = 128; s > 0; s >>= 1) {
        if (tid < s) { sh1[tid] += sh1[tid+s]; sh2[tid] += sh2[tid+s]; }
        __syncthreads();
    }
    if (tid == 0) {
        atomicAdd(&g_stats[2*b+0], sh1[0]);
        atomicAdd(&g_stats[2*b+1], sh2[0]);
    }
}

__global__ void finalize_kernel() {
    int b = threadIdx.x;
    if (b < Bz) {
        float n = (float)Tz * (float)Dz;
        float mean = g_stats[2*b] / n;
        float var  = g_stats[2*b+1] / n - mean*mean;
        g_mean[b] = mean;
        g_rstd[b] = rsqrtf(var + 1e-5f);
    }
}

// ---------------- launcher ---------------------------------------------------
extern "C" void kernel_launch(void* const* d_in, const int* in_sizes, int n_in,
                              void* d_out, int out_size)
{
    const float* x      = (const float*)d_in[0];
    const float* state  = (const float*)d_in[1];
    const float* W_r    = (const float*)d_in[2];
    const float* W_k    = (const float*)d_in[3];
    const float* W_v    = (const float*)d_in[4];
    const float* W_o    = (const float*)d_in[5];
    const float* tmr    = (const float*)d_in[6];
    const float* tmk    = (const float*)d_in[7];
    const float* tmv    = (const float*)d_in[8];
    const float* tdecay = (const float*)d_in[9];
    const float* tfirst = (const float*)d_in[10];
    const float* gamma  = (const float*)d_in[11];
    const float* beta   = (const float*)d_in[12];
    float* out = (float*)d_out;

    cudaFuncSetAttribute(gemm_qkv, cudaFuncAttributeMaxDynamicSharedMemorySize, GSMEM);
    cudaFuncSetAttribute(gemm_out, cudaFuncAttributeMaxDynamicSharedMemorySize, GSMEM);

    zero_stats_kernel<<<1, 32>>>();
    round_w_kernel<<<dim3(Dz*Dz/4/256, 4), 256>>>(W_r, W_k, W_v, W_o, gamma);
    v12_kernel<<<Dz/4, 128>>>(W_o, gamma, beta);
    mix_kernel<<<(BT*Dz/4 + 255)/256, 256>>>(x, state, tmr, tmk, tmv);

    gemm_qkv<<<dim3(Dz/BNt, BT/BMt, 3), 128, GSMEM>>>();

    wkv_pass1<<<dim3(Kz/256, Bz, NCH), 256>>>(tdecay);
    wkv_pass3<<<dim3(Kz/256, Bz, NCH), 256>>>(state, tdecay, tfirst);

    finalize_kernel<<<1, 32>>>();

    gemm_out<<<dim3(Dz/BNt, BT/BMt), 128, GSMEM>>>(out);
}